// round 1
// baseline (speedup 1.0000x reference)
#include <cuda_runtime.h>
#include <cuda_bf16.h>

#define NNODES 50000
#define NEDGES 600000
#define FDIM   128

// ---------------- scratch (device globals: no allocation allowed) -------------
__device__ int   g_deg[NNODES];
__device__ int   g_rowoff[NNODES + 1];
__device__ int   g_woff[NNODES];
__device__ int   g_csrc[NEDGES];
__device__ float g_cw[NEDGES];
__device__ float g_mean[NNODES * FDIM];
__device__ float g_h[NNODES * FDIM];
__device__ float g_y[NNODES * FDIM];
__device__ float g_stats[256];     // [0:128) colsum, [128:256) colsumsq
__device__ float g_scale[128];
__device__ float g_shift[128];

// ---------------- f32x2 packed-FMA helpers (sm_103a FFMA2 path) ---------------
__device__ __forceinline__ unsigned long long pk2(float x, float y) {
    unsigned long long r;
    asm("mov.b64 %0, {%1, %2};" : "=l"(r) : "f"(x), "f"(y));
    return r;
}
__device__ __forceinline__ unsigned long long pk2s(float x) {
    unsigned long long r;
    asm("mov.b64 %0, {%1, %1};" : "=l"(r) : "f"(x));
    return r;
}
__device__ __forceinline__ void fma2(unsigned long long& d, unsigned long long a, unsigned long long b) {
    asm("fma.rn.f32x2 %0, %1, %2, %0;" : "+l"(d) : "l"(a), "l"(b));
}
__device__ __forceinline__ float2 upk(unsigned long long v) {
    float2 f;
    asm("mov.b64 {%0, %1}, %2;" : "=f"(f.x), "=f"(f.y) : "l"(v));
    return f;
}

// ---------------- CSR build ---------------------------------------------------
__global__ void zero_deg_kernel(int n) {
    int i = blockIdx.x * blockDim.x + threadIdx.x;
    if (i < n) g_deg[i] = 0;
}

__global__ void count_deg_kernel(const int* __restrict__ dst, int e) {
    int i = blockIdx.x * blockDim.x + threadIdx.x;
    if (i < e) atomicAdd(&g_deg[dst[i]], 1);
}

// single-block scan: 1024 threads, warp-shuffle based
__global__ void scan_kernel(int n) {
    __shared__ int ws[32];
    int tid = threadIdx.x, lane = tid & 31, wid = tid >> 5;
    int carry = 0;
    for (int base = 0; base < n; base += 1024) {
        int i = base + tid;
        int v = (i < n) ? g_deg[i] : 0;
        int x = v;
        #pragma unroll
        for (int o = 1; o < 32; o <<= 1) {
            int t = __shfl_up_sync(0xFFFFFFFFu, x, o);
            if (lane >= o) x += t;
        }
        if (lane == 31) ws[wid] = x;
        __syncthreads();
        if (wid == 0) {
            int y = ws[lane];
            #pragma unroll
            for (int o = 1; o < 32; o <<= 1) {
                int t = __shfl_up_sync(0xFFFFFFFFu, y, o);
                if (lane >= o) y += t;
            }
            ws[lane] = y;
        }
        __syncthreads();
        int warpoff = wid ? ws[wid - 1] : 0;
        int excl = x + warpoff - v + carry;
        if (i < n) { g_rowoff[i] = excl; g_woff[i] = excl; }
        int total = ws[31];
        __syncthreads();   // protect ws before next chunk's writes
        carry += total;
    }
    if (tid == 0) g_rowoff[n] = carry;
}

__global__ void scatter_kernel(const int* __restrict__ src, const int* __restrict__ dst,
                               const float* __restrict__ w, int e) {
    int i = blockIdx.x * blockDim.x + threadIdx.x;
    if (i < e) {
        int d = dst[i];
        int p = atomicAdd(&g_woff[d], 1);
        g_csrc[p] = src[i];
        g_cw[p]   = w[i];
    }
}

// ---------------- aggregation: warp per node ----------------------------------
__global__ void aggregate_kernel(const float* __restrict__ X, int n) {
    int warp = (blockIdx.x * blockDim.x + threadIdx.x) >> 5;
    int lane = threadIdx.x & 31;
    if (warp >= n) return;
    int beg = g_rowoff[warp], end = g_rowoff[warp + 1];
    const float4* X4 = (const float4*)X;
    float4 acc = make_float4(0.f, 0.f, 0.f, 0.f);
    int e = beg;
    // unrolled by 2 for MLP
    for (; e + 1 < end; e += 2) {
        int   s0 = g_csrc[e],     s1 = g_csrc[e + 1];
        float w0 = g_cw[e],       w1 = g_cw[e + 1];
        float4 v0 = X4[(long)s0 * 32 + lane];
        float4 v1 = X4[(long)s1 * 32 + lane];
        acc.x += w0 * v0.x + w1 * v1.x;
        acc.y += w0 * v0.y + w1 * v1.y;
        acc.z += w0 * v0.z + w1 * v1.z;
        acc.w += w0 * v0.w + w1 * v1.w;
    }
    if (e < end) {
        int s = g_csrc[e]; float w = g_cw[e];
        float4 v = X4[(long)s * 32 + lane];
        acc.x += w * v.x; acc.y += w * v.y; acc.z += w * v.z; acc.w += w * v.w;
    }
    float inv = 1.0f / fmaxf((float)(end - beg), 1.0f);
    acc.x *= inv; acc.y *= inv; acc.z *= inv; acc.w *= inv;
    ((float4*)g_mean)[(long)warp * 32 + lane] = acc;
}

// ---------------- fused GEMM: C = [A1|A2] @ [W1;W2] + bias --------------------
// Tile 128 rows x TN cols, 256 threads (16x16), micro-tile 8 x (TN/16).
template <int TN>
__global__ void __launch_bounds__(256)
gemm_kernel(const float* __restrict__ A1, const float* __restrict__ A2,
            const float* __restrict__ W1, const float* __restrict__ W2,
            const float* __restrict__ bias, float* __restrict__ C, int M) {
    constexpr int RN = TN / 16;           // 8 or 4 cols per thread
    __shared__ float As[128][36];         // 32-k panel, padded (row = 144B, 16B-aligned)
    __shared__ float Bs[32][TN + 4];      // padded  (row 16B-aligned)

    int tid = threadIdx.x;
    int tx = tid & 15, ty = tid >> 4;
    int row0 = blockIdx.x * 128;

    unsigned long long acc2[8][RN / 2];
    #pragma unroll
    for (int m = 0; m < 8; m++)
        #pragma unroll
        for (int n = 0; n < RN / 2; n++) acc2[m][n] = 0ull;

    #pragma unroll
    for (int half = 0; half < 2; half++) {
        const float* A = half ? A2 : A1;
        const float* W = half ? W2 : W1;
        for (int kp = 0; kp < 128; kp += 32) {
            __syncthreads();
            // load A panel: 128 rows x 32 k = 1024 float4
            #pragma unroll
            for (int it = 0; it < 4; it++) {
                int idx = tid + it * 256;       // 0..1023
                int r = idx >> 3;
                int k4 = idx & 7;
                float4 v = make_float4(0.f, 0.f, 0.f, 0.f);
                int gr = row0 + r;
                if (gr < M) v = *(const float4*)(A + (long)gr * 128 + kp + k4 * 4);
                *(float4*)(&As[r][k4 * 4]) = v;
            }
            // load B panel: 32 k x TN cols
            #pragma unroll
            for (int it = 0; it < TN / 32; it++) {
                int idx = tid + it * 256;       // 0..(32*TN/4 - 1)
                int k = idx / (TN / 4);
                int j4 = idx % (TN / 4);
                float4 v = *(const float4*)(W + (long)(kp + k) * TN + j4 * 4);
                *(float4*)(&Bs[k][j4 * 4]) = v;
            }
            __syncthreads();
            #pragma unroll 8
            for (int k = 0; k < 32; k++) {
                unsigned long long b2[RN / 2];
                #pragma unroll
                for (int n4 = 0; n4 < RN / 4; n4++) {
                    float4 bv = *(const float4*)(&Bs[k][tx * RN + n4 * 4]);
                    b2[n4 * 2]     = pk2(bv.x, bv.y);
                    b2[n4 * 2 + 1] = pk2(bv.z, bv.w);
                }
                #pragma unroll
                for (int m = 0; m < 8; m++) {
                    unsigned long long a2 = pk2s(As[ty * 8 + m][k]);
                    #pragma unroll
                    for (int n = 0; n < RN / 2; n++) fma2(acc2[m][n], a2, b2[n]);
                }
            }
        }
    }
    // epilogue: + bias, store
    #pragma unroll
    for (int m = 0; m < 8; m++) {
        int gr = row0 + ty * 8 + m;
        if (gr < M) {
            #pragma unroll
            for (int n = 0; n < RN / 2; n++) {
                float2 v = upk(acc2[m][n]);
                int col = tx * RN + n * 2;
                v.x += bias[col];
                v.y += bias[col + 1];
                *(float2*)(C + (long)gr * TN + col) = v;
            }
        }
    }
}

// ---------------- BatchNorm ----------------------------------------------------
__global__ void zero_stats_kernel() { g_stats[threadIdx.x] = 0.f; }

__global__ void colstat_kernel(int M) {
    int c = threadIdx.x & 127;
    int rg = threadIdx.x >> 7;           // 0 or 1
    float s = 0.f, sq = 0.f;
    for (int r = blockIdx.x * 2 + rg; r < M; r += gridDim.x * 2) {
        float v = g_h[(long)r * 128 + c];
        s += v; sq += v * v;
    }
    __shared__ float sm[256], sm2[256];
    sm[threadIdx.x] = s; sm2[threadIdx.x] = sq;
    __syncthreads();
    if (threadIdx.x < 128) {
        s  = sm[threadIdx.x]  + sm[threadIdx.x + 128];
        sq = sm2[threadIdx.x] + sm2[threadIdx.x + 128];
        atomicAdd(&g_stats[c], s);
        atomicAdd(&g_stats[128 + c], sq);
    }
}

__global__ void bnprep_kernel(const float* __restrict__ gamma, const float* __restrict__ beta,
                              float invM) {
    int c = threadIdx.x;
    float mu  = g_stats[c] * invM;
    float var = g_stats[128 + c] * invM - mu * mu;
    float s = gamma[c] * rsqrtf(var + 1e-5f);
    g_scale[c] = s;
    g_shift[c] = beta[c] - mu * s;
}

__global__ void bnapply_kernel(int n4) {
    int i = blockIdx.x * blockDim.x + threadIdx.x;
    if (i >= n4) return;
    int c4 = i & 31;
    float4 v  = ((const float4*)g_h)[i];
    float4 sc = ((const float4*)g_scale)[c4];
    float4 sh = ((const float4*)g_shift)[c4];
    float4 r;
    r.x = fmaxf(fmaf(v.x, sc.x, sh.x), 0.f);
    r.y = fmaxf(fmaf(v.y, sc.y, sh.y), 0.f);
    r.z = fmaxf(fmaf(v.z, sc.z, sh.z), 0.f);
    r.w = fmaxf(fmaf(v.w, sc.w, sh.w), 0.f);
    ((float4*)g_y)[i] = r;
}

// ---------------- launch -------------------------------------------------------
extern "C" void kernel_launch(void* const* d_in, const int* in_sizes, int n_in,
                              void* d_out, int out_size) {
    const float* x   = (const float*)d_in[0];
    const int*   ei  = (const int*)d_in[1];     // [2, E]: [0:E) src, [E:2E) dst
    const float* ew  = (const float*)d_in[2];
    const float* Wl0 = (const float*)d_in[3];
    const float* Wr0 = (const float*)d_in[4];
    const float* b0  = (const float*)d_in[5];
    const float* Wl1 = (const float*)d_in[6];
    const float* Wr1 = (const float*)d_in[7];
    const float* b1  = (const float*)d_in[8];
    const float* Wl2 = (const float*)d_in[9];
    const float* Wr2 = (const float*)d_in[10];
    const float* b2  = (const float*)d_in[11];
    const float* g0  = (const float*)d_in[12];
    const float* be0 = (const float*)d_in[13];
    const float* g1  = (const float*)d_in[14];
    const float* be1 = (const float*)d_in[15];
    float* out = (float*)d_out;

    int N = in_sizes[0] / FDIM;
    int E = in_sizes[2];

    float *mean, *h, *y;
    cudaGetSymbolAddress((void**)&mean, g_mean);
    cudaGetSymbolAddress((void**)&h,    g_h);
    cudaGetSymbolAddress((void**)&y,    g_y);

    const int T = 256;
    int gE = (E + T - 1) / T;
    int gNodeWarps = (N + 7) / 8;        // 8 warps per block
    int gGemm = (N + 127) / 128;
    int gApply = (N * 32 + T - 1) / T;   // N*128/4 float4s

    // CSR build (graph shared by all 3 layers)
    zero_deg_kernel<<<(N + T - 1) / T, T>>>(N);
    count_deg_kernel<<<gE, T>>>(ei + E, E);
    scan_kernel<<<1, 1024>>>(N);
    scatter_kernel<<<gE, T>>>(ei, ei + E, ew, E);

    float invM = 1.0f / (float)N;

    // ----- layer 0 -----
    aggregate_kernel<<<gNodeWarps, T>>>(x, N);
    gemm_kernel<128><<<gGemm, T>>>(mean, x, Wl0, Wr0, b0, h, N);
    zero_stats_kernel<<<1, 256>>>();
    colstat_kernel<<<256, 256>>>(N);
    bnprep_kernel<<<1, 128>>>(g0, be0, invM);
    bnapply_kernel<<<gApply, T>>>(N * 32);

    // ----- layer 1 -----
    aggregate_kernel<<<gNodeWarps, T>>>(y, N);
    gemm_kernel<128><<<gGemm, T>>>(mean, y, Wl1, Wr1, b1, h, N);
    zero_stats_kernel<<<1, 256>>>();
    colstat_kernel<<<256, 256>>>(N);
    bnprep_kernel<<<1, 128>>>(g1, be1, invM);
    bnapply_kernel<<<gApply, T>>>(N * 32);

    // ----- layer 2 (output, 64 cols) -----
    aggregate_kernel<<<gNodeWarps, T>>>(y, N);
    gemm_kernel<64><<<gGemm, T>>>(mean, y, Wl2, Wr2, b2, out, N);
}

// round 3
// speedup vs baseline: 1.2641x; 1.2641x over previous
#include <cuda_runtime.h>
#include <cuda_bf16.h>
#include <cstdint>

#define NNODES 50000
#define NEDGES 600000

// ---------------- scratch (device globals: no allocation allowed) -------------
__device__ int   g_deg[NNODES];
__device__ int   g_rowoff[NNODES + 1];
__device__ int   g_woff[NNODES];
__device__ int   g_csrc[NEDGES];
__device__ float g_cw[NEDGES];
__device__ float g_h[NNODES * 128];
__device__ float g_y[NNODES * 128];
__device__ __nv_bfloat16 g_xH[NNODES * 128], g_xL[NNODES * 128];
__device__ __nv_bfloat16 g_mH[NNODES * 128], g_mL[NNODES * 128];
__device__ __nv_bfloat16 g_yH[NNODES * 128], g_yL[NNODES * 128];
__device__ __nv_bfloat16 g_BH[128 * 256],    g_BL[128 * 256];   // weights, [n][k]
__device__ float g_stats[256];
__device__ float g_scale[128], g_shift[128];

// ---------------- helpers -----------------------------------------------------
__device__ __forceinline__ uint32_t smem_u32(const void* p) {
    uint32_t a;
    asm("{ .reg .u64 t; cvta.to.shared.u64 t, %1; cvt.u32.u64 %0, t; }" : "=r"(a) : "l"(p));
    return a;
}
__device__ __forceinline__ void ldsm_x4(uint32_t addr, uint32_t r[4]) {
    asm volatile("ldmatrix.sync.aligned.m8n8.x4.shared.b16 {%0,%1,%2,%3}, [%4];"
        : "=r"(r[0]), "=r"(r[1]), "=r"(r[2]), "=r"(r[3]) : "r"(addr));
}
__device__ __forceinline__ void mma16816(float c[4], const uint32_t a[4], uint32_t b0, uint32_t b1) {
    asm volatile("mma.sync.aligned.m16n8k16.row.col.f32.bf16.bf16.f32 "
        "{%0,%1,%2,%3}, {%4,%5,%6,%7}, {%8,%9}, {%0,%1,%2,%3};"
        : "+f"(c[0]), "+f"(c[1]), "+f"(c[2]), "+f"(c[3])
        : "r"(a[0]), "r"(a[1]), "r"(a[2]), "r"(a[3]), "r"(b0), "r"(b1));
}
__device__ __forceinline__ void cpa16(uint32_t dst, const void* src, bool pred) {
    int sz = pred ? 16 : 0;
    asm volatile("cp.async.cg.shared.global [%0], [%1], 16, %2;"
        :: "r"(dst), "l"(src), "r"(sz) : "memory");
}

// ---------------- bf16 hi/lo split helper -------------------------------------
__device__ __forceinline__ void split2(float a, float b, uint32_t& hi, uint32_t& lo) {
    __nv_bfloat162 h = __floats2bfloat162_rn(a, b);
    float ha = __bfloat162float(h.x), hb = __bfloat162float(h.y);
    __nv_bfloat162 l = __floats2bfloat162_rn(a - ha, b - hb);
    hi = *reinterpret_cast<uint32_t*>(&h);
    lo = *reinterpret_cast<uint32_t*>(&l);
}

// ---------------- CSR build ---------------------------------------------------
__global__ void zero_deg_kernel(int n) {
    int i = blockIdx.x * blockDim.x + threadIdx.x;
    if (i < n) g_deg[i] = 0;
}
__global__ void count_deg_kernel(const int* __restrict__ dst, int e) {
    int i = blockIdx.x * blockDim.x + threadIdx.x;
    if (i < e) atomicAdd(&g_deg[dst[i]], 1);
}
__global__ void scan_kernel(int n) {
    __shared__ int ws[32];
    int tid = threadIdx.x, lane = tid & 31, wid = tid >> 5;
    int carry = 0;
    for (int base = 0; base < n; base += 1024) {
        int i = base + tid;
        int v = (i < n) ? g_deg[i] : 0;
        int x = v;
        #pragma unroll
        for (int o = 1; o < 32; o <<= 1) {
            int t = __shfl_up_sync(0xFFFFFFFFu, x, o);
            if (lane >= o) x += t;
        }
        if (lane == 31) ws[wid] = x;
        __syncthreads();
        if (wid == 0) {
            int y = ws[lane];
            #pragma unroll
            for (int o = 1; o < 32; o <<= 1) {
                int t = __shfl_up_sync(0xFFFFFFFFu, y, o);
                if (lane >= o) y += t;
            }
            ws[lane] = y;
        }
        __syncthreads();
        int warpoff = wid ? ws[wid - 1] : 0;
        int excl = x + warpoff - v + carry;
        if (i < n) { g_rowoff[i] = excl; g_woff[i] = excl; }
        int total = ws[31];
        __syncthreads();
        carry += total;
    }
    if (tid == 0) g_rowoff[n] = carry;
}
__global__ void scatter_kernel(const int* __restrict__ src, const int* __restrict__ dst,
                               const float* __restrict__ w, int e) {
    int i = blockIdx.x * blockDim.x + threadIdx.x;
    if (i < e) {
        int d = dst[i];
        int p = atomicAdd(&g_woff[d], 1);
        g_csrc[p] = src[i];
        g_cw[p]   = w[i];
    }
}

// ---------------- aggregation: warp per node, emits bf16 hi/lo -----------------
__global__ void aggregate_kernel(const float* __restrict__ X, int n) {
    int warp = (blockIdx.x * blockDim.x + threadIdx.x) >> 5;
    int lane = threadIdx.x & 31;
    if (warp >= n) return;
    int beg = g_rowoff[warp], end = g_rowoff[warp + 1];
    const float4* X4 = (const float4*)X;
    float4 acc = make_float4(0.f, 0.f, 0.f, 0.f);
    int e = beg;
    for (; e + 1 < end; e += 2) {
        int   s0 = g_csrc[e],     s1 = g_csrc[e + 1];
        float w0 = g_cw[e],       w1 = g_cw[e + 1];
        float4 v0 = X4[(long)s0 * 32 + lane];
        float4 v1 = X4[(long)s1 * 32 + lane];
        acc.x += w0 * v0.x + w1 * v1.x;
        acc.y += w0 * v0.y + w1 * v1.y;
        acc.z += w0 * v0.z + w1 * v1.z;
        acc.w += w0 * v0.w + w1 * v1.w;
    }
    if (e < end) {
        int s = g_csrc[e]; float w = g_cw[e];
        float4 v = X4[(long)s * 32 + lane];
        acc.x += w * v.x; acc.y += w * v.y; acc.z += w * v.z; acc.w += w * v.w;
    }
    float inv = 1.0f / fmaxf((float)(end - beg), 1.0f);
    acc.x *= inv; acc.y *= inv; acc.z *= inv; acc.w *= inv;
    uint32_t h01, l01, h23, l23;
    split2(acc.x, acc.y, h01, l01);
    split2(acc.z, acc.w, h23, l23);
    ((uint2*)g_mH)[(long)warp * 32 + lane] = make_uint2(h01, h23);
    ((uint2*)g_mL)[(long)warp * 32 + lane] = make_uint2(l01, l23);
}

// ---------------- fp32 -> bf16 hi/lo conversion (for x) ------------------------
__global__ void conv_kernel(const float* __restrict__ X, __nv_bfloat16* __restrict__ H,
                            __nv_bfloat16* __restrict__ L, int n4) {
    int i = blockIdx.x * blockDim.x + threadIdx.x;
    if (i >= n4) return;
    float4 v = ((const float4*)X)[i];
    uint32_t h01, l01, h23, l23;
    split2(v.x, v.y, h01, l01);
    split2(v.z, v.w, h23, l23);
    ((uint2*)H)[i] = make_uint2(h01, h23);
    ((uint2*)L)[i] = make_uint2(l01, l23);
}

// ---------------- weight prep: B[n][k] = W[k][n], bf16 hi/lo -------------------
__global__ void wprep_kernel(const float* __restrict__ Wl, const float* __restrict__ Wr,
                             int TN, int total) {
    int t = blockIdx.x * blockDim.x + threadIdx.x;
    if (t >= total) return;
    int n = t >> 8;
    int k = t & 255;
    float v = (k < 128) ? Wl[k * TN + n] : Wr[(k - 128) * TN + n];
    __nv_bfloat16 h = __float2bfloat16_rn(v);
    g_BH[t] = h;
    g_BL[t] = __float2bfloat16_rn(v - __bfloat162float(h));
}

// ---------------- mma.sync GEMM: C[M,TN] = [mean|other] @ B^T + bias -----------
// 3-term bf16 split: A_hi.B_hi + A_lo.B_hi + A_hi.B_lo
// 24 k-chunks of 32: term(3) x half(2) x kc(4). cp.async double buffered.
template <int TN>
__global__ void __launch_bounds__(256)
gemm_mma(const __nv_bfloat16* __restrict__ mH, const __nv_bfloat16* __restrict__ mL,
         const __nv_bfloat16* __restrict__ aH, const __nv_bfloat16* __restrict__ aL,
         const float* __restrict__ bias, float* __restrict__ C, int M) {
    constexpr int NWC = TN / 2;      // warp col span
    constexpr int NF  = NWC / 8;     // n8 fragments per warp
    __shared__ __align__(16) char sA[2][128 * 80];
    __shared__ __align__(16) char sB[2][TN * 80];

    const int tid = threadIdx.x;
    const int lane = tid & 31, wid = tid >> 5;
    const int wm = wid & 3, wn = wid >> 2;
    const int row0 = blockIdx.x * 128;

    float acc[2][NF][4];
    #pragma unroll
    for (int mb = 0; mb < 2; mb++)
        #pragma unroll
        for (int f = 0; f < NF; f++)
            #pragma unroll
            for (int q = 0; q < 4; q++) acc[mb][f][q] = 0.f;

    const uint32_t aBase[2] = { smem_u32(sA[0]), smem_u32(sA[1]) };
    const uint32_t bBase[2] = { smem_u32(sB[0]), smem_u32(sB[1]) };

    auto load_chunk = [&](int ch, int buf) {
        const int term = ch >> 3, half = (ch >> 2) & 1, kc = ch & 3;
        const __nv_bfloat16* Ap = (term == 1) ? (half ? aL : mL) : (half ? aH : mH);
        const __nv_bfloat16* Bp = (term == 2) ? g_BL : g_BH;
        const int acol = kc * 32;
        const int bcol = half * 128 + kc * 32;
        #pragma unroll
        for (int t = 0; t < 2; t++) {
            int idx = tid + t * 256;
            int r = idx >> 2, c = idx & 3;
            int gr = row0 + r;
            cpa16(aBase[buf] + r * 80 + c * 16,
                  Ap + (long)gr * 128 + acol + c * 8, gr < M);
        }
        #pragma unroll
        for (int t = 0; t < TN / 64; t++) {
            int idx = tid + t * 256;
            int n = idx >> 2, c = idx & 3;
            cpa16(bBase[buf] + n * 80 + c * 16, Bp + n * 256 + bcol + c * 8, true);
        }
        asm volatile("cp.async.commit_group;" ::: "memory");
    };

    load_chunk(0, 0);

    for (int ch = 0; ch < 24; ch++) {
        const int buf = ch & 1;
        if (ch + 1 < 24) {
            load_chunk(ch + 1, buf ^ 1);
            asm volatile("cp.async.wait_group 1;" ::: "memory");
        } else {
            asm volatile("cp.async.wait_group 0;" ::: "memory");
        }
        __syncthreads();

        #pragma unroll
        for (int ks = 0; ks < 2; ks++) {
            uint32_t afr[2][4];
            #pragma unroll
            for (int mb = 0; mb < 2; mb++) {
                uint32_t addr = aBase[buf]
                    + (wm * 32 + mb * 16 + (lane & 15)) * 80
                    + ks * 32 + ((lane >> 4) << 4);
                ldsm_x4(addr, afr[mb]);
            }
            #pragma unroll
            for (int f = 0; f < NF / 2; f++) {
                int n = wn * NWC + f * 16 + (lane & 7) + ((lane >> 3) & 1) * 8;
                uint32_t addr = bBase[buf] + n * 80 + ks * 32 + ((lane >> 4) << 4);
                uint32_t bfr[4];
                ldsm_x4(addr, bfr);
                #pragma unroll
                for (int mb = 0; mb < 2; mb++) {
                    mma16816(acc[mb][2 * f],     afr[mb], bfr[0], bfr[2]);
                    mma16816(acc[mb][2 * f + 1], afr[mb], bfr[1], bfr[3]);
                }
            }
        }
        __syncthreads();
    }

    // epilogue: + bias, store fp32
    const int rA = row0 + wm * 32 + (lane >> 2);
    const int cbase = wn * NWC + (lane & 3) * 2;
    #pragma unroll
    for (int mb = 0; mb < 2; mb++) {
        #pragma unroll
        for (int nf = 0; nf < NF; nf++) {
            int col = cbase + nf * 8;
            float bx = bias[col], by = bias[col + 1];
            int r0r = rA + mb * 16;
            if (r0r < M) {
                float2 v = make_float2(acc[mb][nf][0] + bx, acc[mb][nf][1] + by);
                *(float2*)(C + (long)r0r * TN + col) = v;
            }
            int r1r = r0r + 8;
            if (r1r < M) {
                float2 v = make_float2(acc[mb][nf][2] + bx, acc[mb][nf][3] + by);
                *(float2*)(C + (long)r1r * TN + col) = v;
            }
        }
    }
}

// ---------------- BatchNorm ----------------------------------------------------
__global__ void zero_stats_kernel() { g_stats[threadIdx.x] = 0.f; }

__global__ void colstat_kernel(int M) {
    int c = threadIdx.x & 127;
    int rg = threadIdx.x >> 7;
    float s = 0.f, sq = 0.f;
    for (int r = blockIdx.x * 2 + rg; r < M; r += gridDim.x * 2) {
        float v = g_h[(long)r * 128 + c];
        s += v; sq += v * v;
    }
    __shared__ float sm[256], sm2[256];
    sm[threadIdx.x] = s; sm2[threadIdx.x] = sq;
    __syncthreads();
    if (threadIdx.x < 128) {
        s  = sm[threadIdx.x]  + sm[threadIdx.x + 128];
        sq = sm2[threadIdx.x] + sm2[threadIdx.x + 128];
        atomicAdd(&g_stats[c], s);
        atomicAdd(&g_stats[128 + c], sq);
    }
}

__global__ void bnprep_kernel(const float* __restrict__ gamma, const float* __restrict__ beta,
                              float invM) {
    int c = threadIdx.x;
    float mu  = g_stats[c] * invM;
    float var = g_stats[128 + c] * invM - mu * mu;
    float s = gamma[c] * rsqrtf(var + 1e-5f);
    g_scale[c] = s;
    g_shift[c] = beta[c] - mu * s;
}

// apply BN+ReLU: writes fp32 y (for aggregation) + bf16 hi/lo (for GEMM)
__global__ void bnapply_kernel(int n4) {
    int i = blockIdx.x * blockDim.x + threadIdx.x;
    if (i >= n4) return;
    int c4 = i & 31;
    float4 v  = ((const float4*)g_h)[i];
    float4 sc = ((const float4*)g_scale)[c4];
    float4 sh = ((const float4*)g_shift)[c4];
    float4 r;
    r.x = fmaxf(fmaf(v.x, sc.x, sh.x), 0.f);
    r.y = fmaxf(fmaf(v.y, sc.y, sh.y), 0.f);
    r.z = fmaxf(fmaf(v.z, sc.z, sh.z), 0.f);
    r.w = fmaxf(fmaf(v.w, sc.w, sh.w), 0.f);
    ((float4*)g_y)[i] = r;
    uint32_t h01, l01, h23, l23;
    split2(r.x, r.y, h01, l01);
    split2(r.z, r.w, h23, l23);
    ((uint2*)g_yH)[i] = make_uint2(h01, h23);
    ((uint2*)g_yL)[i] = make_uint2(l01, l23);
}

// ---------------- launch -------------------------------------------------------
extern "C" void kernel_launch(void* const* d_in, const int* in_sizes, int n_in,
                              void* d_out, int out_size) {
    const float* x   = (const float*)d_in[0];
    const int*   ei  = (const int*)d_in[1];
    const float* ew  = (const float*)d_in[2];
    const float* Wl0 = (const float*)d_in[3];
    const float* Wr0 = (const float*)d_in[4];
    const float* b0  = (const float*)d_in[5];
    const float* Wl1 = (const float*)d_in[6];
    const float* Wr1 = (const float*)d_in[7];
    const float* b1  = (const float*)d_in[8];
    const float* Wl2 = (const float*)d_in[9];
    const float* Wr2 = (const float*)d_in[10];
    const float* b2  = (const float*)d_in[11];
    const float* g0  = (const float*)d_in[12];
    const float* be0 = (const float*)d_in[13];
    const float* g1  = (const float*)d_in[14];
    const float* be1 = (const float*)d_in[15];
    float* out = (float*)d_out;

    int N = in_sizes[0] / 128;
    int E = in_sizes[2];

    float *h, *y;
    __nv_bfloat16 *xH, *xL, *mH, *mL, *yH, *yL;
    cudaGetSymbolAddress((void**)&h,  g_h);
    cudaGetSymbolAddress((void**)&y,  g_y);
    cudaGetSymbolAddress((void**)&xH, g_xH);
    cudaGetSymbolAddress((void**)&xL, g_xL);
    cudaGetSymbolAddress((void**)&mH, g_mH);
    cudaGetSymbolAddress((void**)&mL, g_mL);
    cudaGetSymbolAddress((void**)&yH, g_yH);
    cudaGetSymbolAddress((void**)&yL, g_yL);

    const int T = 256;
    int gE = (E + T - 1) / T;
    int gNodeWarps = (N + 7) / 8;
    int gGemm = (N + 127) / 128;
    int gApply = (N * 32 + T - 1) / T;

    // CSR build (graph shared by all 3 layers)
    zero_deg_kernel<<<(N + T - 1) / T, T>>>(N);
    count_deg_kernel<<<gE, T>>>(ei + E, E);
    scan_kernel<<<1, 1024>>>(N);
    scatter_kernel<<<gE, T>>>(ei, ei + E, ew, E);

    // x -> bf16 hi/lo
    conv_kernel<<<gApply, T>>>(x, xH, xL, N * 32);

    float invM = 1.0f / (float)N;

    // ----- layer 0 -----
    wprep_kernel<<<128, 256>>>(Wl0, Wr0, 128, 128 * 256);
    aggregate_kernel<<<gNodeWarps, T>>>(x, N);
    gemm_mma<128><<<gGemm, T>>>(mH, mL, xH, xL, b0, h, N);
    zero_stats_kernel<<<1, 256>>>();
    colstat_kernel<<<256, 256>>>(N);
    bnprep_kernel<<<1, 128>>>(g0, be0, invM);
    bnapply_kernel<<<gApply, T>>>(N * 32);

    // ----- layer 1 -----
    wprep_kernel<<<128, 256>>>(Wl1, Wr1, 128, 128 * 256);
    aggregate_kernel<<<gNodeWarps, T>>>(y, N);
    gemm_mma<128><<<gGemm, T>>>(mH, mL, yH, yL, b1, h, N);
    zero_stats_kernel<<<1, 256>>>();
    colstat_kernel<<<256, 256>>>(N);
    bnprep_kernel<<<1, 128>>>(g1, be1, invM);
    bnapply_kernel<<<gApply, T>>>(N * 32);

    // ----- layer 2 (output, 64 cols) -----
    wprep_kernel<<<64, 256>>>(Wl2, Wr2, 64, 64 * 256);
    aggregate_kernel<<<gNodeWarps, T>>>(y, N);
    gemm_mma<64><<<gGemm, T>>>(mH, mL, yH, yL, b2, out, N);
}

// round 4
// speedup vs baseline: 1.4670x; 1.1605x over previous
#include <cuda_runtime.h>
#include <cuda_bf16.h>
#include <cstdint>

#define NNODES 50000
#define NEDGES 600000

// ---------------- scratch (device globals) -------------------------------------
__device__ int   g_deg[NNODES];
__device__ int   g_rowoff[NNODES + 1];
__device__ int   g_woff[NNODES];
__device__ int   g_csrc[NEDGES];
__device__ float g_cw[NEDGES];
__device__ float g_h[NNODES * 128];
__device__ __nv_bfloat16 g_xH[NNODES * 128], g_xL[NNODES * 128];
__device__ __nv_bfloat16 g_mH[NNODES * 128], g_mL[NNODES * 128];
__device__ __nv_bfloat16 g_yH[NNODES * 128], g_yL[NNODES * 128];
__device__ __nv_bfloat16 g_BH[81920], g_BL[81920];   // W0(32768) W1(32768) W2(16384), [n][k]
__device__ float g_statsA[512];                       // layer0: [0,256) ; layer1: [256,512)

// ---------------- helpers ------------------------------------------------------
__device__ __forceinline__ uint32_t smem_u32(const void* p) {
    uint32_t a;
    asm("{ .reg .u64 t; cvta.to.shared.u64 t, %1; cvt.u32.u64 %0, t; }" : "=r"(a) : "l"(p));
    return a;
}
__device__ __forceinline__ void ldsm_x4(uint32_t addr, uint32_t r[4]) {
    asm volatile("ldmatrix.sync.aligned.m8n8.x4.shared.b16 {%0,%1,%2,%3}, [%4];"
        : "=r"(r[0]), "=r"(r[1]), "=r"(r[2]), "=r"(r[3]) : "r"(addr));
}
__device__ __forceinline__ void mma16816(float c[4], const uint32_t a[4], uint32_t b0, uint32_t b1) {
    asm volatile("mma.sync.aligned.m16n8k16.row.col.f32.bf16.bf16.f32 "
        "{%0,%1,%2,%3}, {%4,%5,%6,%7}, {%8,%9}, {%0,%1,%2,%3};"
        : "+f"(c[0]), "+f"(c[1]), "+f"(c[2]), "+f"(c[3])
        : "r"(a[0]), "r"(a[1]), "r"(a[2]), "r"(a[3]), "r"(b0), "r"(b1));
}
__device__ __forceinline__ void cpa16(uint32_t dst, const void* src, bool pred) {
    int sz = pred ? 16 : 0;
    asm volatile("cp.async.cg.shared.global [%0], [%1], 16, %2;"
        :: "r"(dst), "l"(src), "r"(sz) : "memory");
}
__device__ __forceinline__ void split2(float a, float b, uint32_t& hi, uint32_t& lo) {
    __nv_bfloat162 h = __floats2bfloat162_rn(a, b);
    float ha = __bfloat162float(h.x), hb = __bfloat162float(h.y);
    __nv_bfloat162 l = __floats2bfloat162_rn(a - ha, b - hb);
    hi = *reinterpret_cast<uint32_t*>(&h);
    lo = *reinterpret_cast<uint32_t*>(&l);
}
// BN coefficients from raw stats (recomputed inline wherever needed)
__device__ __forceinline__ void bn_coef(const float* __restrict__ stats,
                                        const float* __restrict__ gamma,
                                        const float* __restrict__ beta,
                                        float invM, int c, float& sc, float& sh) {
    float mu  = stats[c] * invM;
    float var = stats[128 + c] * invM - mu * mu;
    float s = gamma[c] * rsqrtf(var + 1e-5f);
    sc = s;
    sh = beta[c] - mu * s;
}

// ---------------- prep: x split + weight transpose/split + zeroing -------------
__global__ void prep_kernel(const float* __restrict__ x,
                            const float* __restrict__ Wl0, const float* __restrict__ Wr0,
                            const float* __restrict__ Wl1, const float* __restrict__ Wr1,
                            const float* __restrict__ Wl2, const float* __restrict__ Wr2,
                            int n4) {
    int gid = blockIdx.x * blockDim.x + threadIdx.x;
    if (gid < n4) {
        float4 v = ((const float4*)x)[gid];
        uint32_t h01, l01, h23, l23;
        split2(v.x, v.y, h01, l01);
        split2(v.z, v.w, h23, l23);
        ((uint2*)g_xH)[gid] = make_uint2(h01, h23);
        ((uint2*)g_xL)[gid] = make_uint2(l01, l23);
    }
    if (gid < NNODES) g_deg[gid] = 0;
    if (gid < 512) g_statsA[gid] = 0.f;
    if (gid < 81920) {
        const float *Wl, *Wr; int TN, t, off;
        if (gid < 32768)      { Wl = Wl0; Wr = Wr0; TN = 128; t = gid;         off = 0; }
        else if (gid < 65536) { Wl = Wl1; Wr = Wr1; TN = 128; t = gid - 32768; off = 32768; }
        else                  { Wl = Wl2; Wr = Wr2; TN = 64;  t = gid - 65536; off = 65536; }
        int n = t >> 8, k = t & 255;
        float v = (k < 128) ? Wl[k * TN + n] : Wr[(k - 128) * TN + n];
        __nv_bfloat16 h = __float2bfloat16_rn(v);
        g_BH[off + t] = h;
        g_BL[off + t] = __float2bfloat16_rn(v - __bfloat162float(h));
    }
}

// ---------------- CSR build ----------------------------------------------------
__global__ void count_deg_kernel(const int* __restrict__ dst, int e) {
    int i = blockIdx.x * blockDim.x + threadIdx.x;
    if (i < e) atomicAdd(&g_deg[dst[i]], 1);
}
__global__ void scan_kernel(int n) {
    __shared__ int ws[32];
    int tid = threadIdx.x, lane = tid & 31, wid = tid >> 5;
    int carry = 0;
    for (int base = 0; base < n; base += 1024) {
        int i = base + tid;
        int v = (i < n) ? g_deg[i] : 0;
        int x = v;
        #pragma unroll
        for (int o = 1; o < 32; o <<= 1) {
            int t = __shfl_up_sync(0xFFFFFFFFu, x, o);
            if (lane >= o) x += t;
        }
        if (lane == 31) ws[wid] = x;
        __syncthreads();
        if (wid == 0) {
            int y = ws[lane];
            #pragma unroll
            for (int o = 1; o < 32; o <<= 1) {
                int t = __shfl_up_sync(0xFFFFFFFFu, y, o);
                if (lane >= o) y += t;
            }
            ws[lane] = y;
        }
        __syncthreads();
        int warpoff = wid ? ws[wid - 1] : 0;
        int excl = x + warpoff - v + carry;
        if (i < n) { g_rowoff[i] = excl; g_woff[i] = excl; }
        int total = ws[31];
        __syncthreads();
        carry += total;
    }
    if (tid == 0) g_rowoff[n] = carry;
}
__global__ void scatter_kernel(const int* __restrict__ src, const int* __restrict__ dst,
                               const float* __restrict__ w, int e) {
    int i = blockIdx.x * blockDim.x + threadIdx.x;
    if (i < e) {
        int d = dst[i];
        int p = atomicAdd(&g_woff[d], 1);
        g_csrc[p] = src[i];
        g_cw[p]   = w[i];
    }
}

// ---------------- aggregation: warp/node, optional BN+ReLU on the fly ----------
template <bool BN>
__global__ void aggregate_kernel(const float* __restrict__ X,
                                 const float* __restrict__ stats,
                                 const float* __restrict__ gamma,
                                 const float* __restrict__ beta,
                                 float invM, int n) {
    int warp = (blockIdx.x * blockDim.x + threadIdx.x) >> 5;
    int lane = threadIdx.x & 31;
    if (warp >= n) return;

    float4 sc = make_float4(1.f, 1.f, 1.f, 1.f), sh = make_float4(0.f, 0.f, 0.f, 0.f);
    if (BN) {
        bn_coef(stats, gamma, beta, invM, lane * 4 + 0, sc.x, sh.x);
        bn_coef(stats, gamma, beta, invM, lane * 4 + 1, sc.y, sh.y);
        bn_coef(stats, gamma, beta, invM, lane * 4 + 2, sc.z, sh.z);
        bn_coef(stats, gamma, beta, invM, lane * 4 + 3, sc.w, sh.w);
    }

    int beg = g_rowoff[warp], end = g_rowoff[warp + 1];
    const float4* X4 = (const float4*)X;
    float4 acc = make_float4(0.f, 0.f, 0.f, 0.f);
    int e = beg;
    for (; e + 1 < end; e += 2) {
        int   s0 = g_csrc[e],     s1 = g_csrc[e + 1];
        float w0 = g_cw[e],       w1 = g_cw[e + 1];
        float4 v0 = X4[(long)s0 * 32 + lane];
        float4 v1 = X4[(long)s1 * 32 + lane];
        if (BN) {
            v0.x = fmaxf(fmaf(v0.x, sc.x, sh.x), 0.f); v1.x = fmaxf(fmaf(v1.x, sc.x, sh.x), 0.f);
            v0.y = fmaxf(fmaf(v0.y, sc.y, sh.y), 0.f); v1.y = fmaxf(fmaf(v1.y, sc.y, sh.y), 0.f);
            v0.z = fmaxf(fmaf(v0.z, sc.z, sh.z), 0.f); v1.z = fmaxf(fmaf(v1.z, sc.z, sh.z), 0.f);
            v0.w = fmaxf(fmaf(v0.w, sc.w, sh.w), 0.f); v1.w = fmaxf(fmaf(v1.w, sc.w, sh.w), 0.f);
        }
        acc.x += w0 * v0.x + w1 * v1.x;
        acc.y += w0 * v0.y + w1 * v1.y;
        acc.z += w0 * v0.z + w1 * v1.z;
        acc.w += w0 * v0.w + w1 * v1.w;
    }
    if (e < end) {
        int s = g_csrc[e]; float w = g_cw[e];
        float4 v = X4[(long)s * 32 + lane];
        if (BN) {
            v.x = fmaxf(fmaf(v.x, sc.x, sh.x), 0.f);
            v.y = fmaxf(fmaf(v.y, sc.y, sh.y), 0.f);
            v.z = fmaxf(fmaf(v.z, sc.z, sh.z), 0.f);
            v.w = fmaxf(fmaf(v.w, sc.w, sh.w), 0.f);
        }
        acc.x += w * v.x; acc.y += w * v.y; acc.z += w * v.z; acc.w += w * v.w;
    }
    float inv = 1.0f / fmaxf((float)(end - beg), 1.0f);
    acc.x *= inv; acc.y *= inv; acc.z *= inv; acc.w *= inv;
    uint32_t h01, l01, h23, l23;
    split2(acc.x, acc.y, h01, l01);
    split2(acc.z, acc.w, h23, l23);
    ((uint2*)g_mH)[(long)warp * 32 + lane] = make_uint2(h01, h23);
    ((uint2*)g_mL)[(long)warp * 32 + lane] = make_uint2(l01, l23);
}

// ---------------- bnapply (slim): h -> yH/yL (BN+ReLU, bf16 hi/lo) --------------
__global__ void bnapply_kernel(const float* __restrict__ stats,
                               const float* __restrict__ gamma,
                               const float* __restrict__ beta,
                               float invM, int n4) {
    int i = blockIdx.x * blockDim.x + threadIdx.x;
    if (i >= n4) return;
    int c0 = (i & 31) * 4;
    float4 sc, sh;
    bn_coef(stats, gamma, beta, invM, c0 + 0, sc.x, sh.x);
    bn_coef(stats, gamma, beta, invM, c0 + 1, sc.y, sh.y);
    bn_coef(stats, gamma, beta, invM, c0 + 2, sc.z, sh.z);
    bn_coef(stats, gamma, beta, invM, c0 + 3, sc.w, sh.w);
    float4 v = ((const float4*)g_h)[i];
    float4 r;
    r.x = fmaxf(fmaf(v.x, sc.x, sh.x), 0.f);
    r.y = fmaxf(fmaf(v.y, sc.y, sh.y), 0.f);
    r.z = fmaxf(fmaf(v.z, sc.z, sh.z), 0.f);
    r.w = fmaxf(fmaf(v.w, sc.w, sh.w), 0.f);
    uint32_t h01, l01, h23, l23;
    split2(r.x, r.y, h01, l01);
    split2(r.z, r.w, h23, l23);
    ((uint2*)g_yH)[i] = make_uint2(h01, h23);
    ((uint2*)g_yL)[i] = make_uint2(l01, l23);
}

// ---------------- mma.sync GEMM v2: shared A-hi across B-hi/B-lo terms ----------
// 8 k-chunks of 32; per chunk load {Ahi, Alo, Bhi, Blo}, compute 3 term combos.
// Optional fused column stats (sum, sumsq) for BN.
template <int TN, bool STATS>
__global__ void __launch_bounds__(256)
gemm2(const __nv_bfloat16* __restrict__ mH, const __nv_bfloat16* __restrict__ mL,
      const __nv_bfloat16* __restrict__ rH, const __nv_bfloat16* __restrict__ rL,
      const __nv_bfloat16* __restrict__ BH, const __nv_bfloat16* __restrict__ BL,
      const float* __restrict__ bias, float* __restrict__ C,
      float* __restrict__ stats, int M) {
    constexpr int NWC = TN / 2;
    constexpr int NF  = NWC / 8;
    constexpr int offAhi = 0;
    constexpr int offAlo = 128 * 80;
    constexpr int offBhi = 2 * 128 * 80;
    constexpr int offBlo = 2 * 128 * 80 + TN * 80;
    constexpr int STAGE  = 2 * 128 * 80 + 2 * TN * 80;

    extern __shared__ __align__(16) char smem[];
    const uint32_t sbase = smem_u32(smem);

    const int tid = threadIdx.x;
    const int lane = tid & 31, wid = tid >> 5;
    const int wm = wid & 3, wn = wid >> 2;
    const int row0 = blockIdx.x * 128;

    float acc[2][NF][4];
    #pragma unroll
    for (int mb = 0; mb < 2; mb++)
        #pragma unroll
        for (int f = 0; f < NF; f++)
            #pragma unroll
            for (int q = 0; q < 4; q++) acc[mb][f][q] = 0.f;

    auto load_chunk = [&](int ch, int buf) {
        const int half = ch >> 2, q = ch & 3;
        const __nv_bfloat16* Ah = half ? rH : mH;
        const __nv_bfloat16* Al = half ? rL : mL;
        const int acol = q * 32;
        const int bcol = half * 128 + q * 32;
        const uint32_t base = sbase + buf * STAGE;
        #pragma unroll
        for (int t = 0; t < 2; t++) {
            int idx = tid + t * 256;
            int r = idx >> 2, c = idx & 3;
            int gr = row0 + r;
            const long aoff = (long)gr * 128 + acol + c * 8;
            cpa16(base + offAhi + r * 80 + c * 16, Ah + aoff, gr < M);
            cpa16(base + offAlo + r * 80 + c * 16, Al + aoff, gr < M);
        }
        #pragma unroll
        for (int t = 0; t < TN / 64; t++) {
            int idx = tid + t * 256;
            int n = idx >> 2, c = idx & 3;
            const long boff = (long)n * 256 + bcol + c * 8;
            cpa16(base + offBhi + n * 80 + c * 16, BH + boff, true);
            cpa16(base + offBlo + n * 80 + c * 16, BL + boff, true);
        }
        asm volatile("cp.async.commit_group;" ::: "memory");
    };

    load_chunk(0, 0);

    for (int ch = 0; ch < 8; ch++) {
        const int buf = ch & 1;
        if (ch + 1 < 8) {
            load_chunk(ch + 1, buf ^ 1);
            asm volatile("cp.async.wait_group 1;" ::: "memory");
        } else {
            asm volatile("cp.async.wait_group 0;" ::: "memory");
        }
        __syncthreads();
        const uint32_t base = sbase + buf * STAGE;

        #pragma unroll
        for (int ks = 0; ks < 2; ks++) {
            uint32_t aH2[2][4], aL2[2][4];
            #pragma unroll
            for (int mb = 0; mb < 2; mb++) {
                uint32_t rterm = (wm * 32 + mb * 16 + (lane & 15)) * 80
                               + ks * 32 + ((lane >> 4) << 4);
                ldsm_x4(base + offAhi + rterm, aH2[mb]);
                ldsm_x4(base + offAlo + rterm, aL2[mb]);
            }
            #pragma unroll
            for (int f = 0; f < NF / 2; f++) {
                int n = wn * NWC + f * 16 + (lane & 7) + ((lane >> 3) & 1) * 8;
                uint32_t boff = n * 80 + ks * 32 + ((lane >> 4) << 4);
                uint32_t bH[4], bL[4];
                ldsm_x4(base + offBhi + boff, bH);
                ldsm_x4(base + offBlo + boff, bL);
                #pragma unroll
                for (int mb = 0; mb < 2; mb++) {
                    mma16816(acc[mb][2 * f],     aH2[mb], bH[0], bH[2]);
                    mma16816(acc[mb][2 * f + 1], aH2[mb], bH[1], bH[3]);
                    mma16816(acc[mb][2 * f],     aL2[mb], bH[0], bH[2]);
                    mma16816(acc[mb][2 * f + 1], aL2[mb], bH[1], bH[3]);
                    mma16816(acc[mb][2 * f],     aH2[mb], bL[0], bL[2]);
                    mma16816(acc[mb][2 * f + 1], aH2[mb], bL[1], bL[3]);
                }
            }
        }
        __syncthreads();
    }

    // epilogue: + bias, store, optional fused column stats
    const int rA = row0 + wm * 32 + (lane >> 2);
    const int cbase = wn * NWC + (lane & 3) * 2;
    #pragma unroll
    for (int nf = 0; nf < NF; nf++) {
        int col = cbase + nf * 8;
        float bx = bias[col], by = bias[col + 1];
        float s0 = 0.f, q0 = 0.f, s1 = 0.f, q1 = 0.f;
        #pragma unroll
        for (int mb = 0; mb < 2; mb++) {
            int r0r = rA + mb * 16;
            if (r0r < M) {
                float vx = acc[mb][nf][0] + bx, vy = acc[mb][nf][1] + by;
                *(float2*)(C + (long)r0r * TN + col) = make_float2(vx, vy);
                if (STATS) { s0 += vx; q0 += vx * vx; s1 += vy; q1 += vy * vy; }
            }
            int r1r = r0r + 8;
            if (r1r < M) {
                float vx = acc[mb][nf][2] + bx, vy = acc[mb][nf][3] + by;
                *(float2*)(C + (long)r1r * TN + col) = make_float2(vx, vy);
                if (STATS) { s0 += vx; q0 += vx * vx; s1 += vy; q1 += vy * vy; }
            }
        }
        if (STATS) {
            #pragma unroll
            for (int o = 4; o < 32; o <<= 1) {
                s0 += __shfl_xor_sync(0xFFFFFFFFu, s0, o);
                q0 += __shfl_xor_sync(0xFFFFFFFFu, q0, o);
                s1 += __shfl_xor_sync(0xFFFFFFFFu, s1, o);
                q1 += __shfl_xor_sync(0xFFFFFFFFu, q1, o);
            }
            if ((lane >> 2) == 0) {
                atomicAdd(&stats[col], s0);
                atomicAdd(&stats[128 + col], q0);
                atomicAdd(&stats[col + 1], s1);
                atomicAdd(&stats[128 + col + 1], q1);
            }
        }
    }
}

// ---------------- launch --------------------------------------------------------
extern "C" void kernel_launch(void* const* d_in, const int* in_sizes, int n_in,
                              void* d_out, int out_size) {
    const float* x   = (const float*)d_in[0];
    const int*   ei  = (const int*)d_in[1];
    const float* ew  = (const float*)d_in[2];
    const float* Wl0 = (const float*)d_in[3];
    const float* Wr0 = (const float*)d_in[4];
    const float* b0  = (const float*)d_in[5];
    const float* Wl1 = (const float*)d_in[6];
    const float* Wr1 = (const float*)d_in[7];
    const float* b1  = (const float*)d_in[8];
    const float* Wl2 = (const float*)d_in[9];
    const float* Wr2 = (const float*)d_in[10];
    const float* b2  = (const float*)d_in[11];
    const float* g0  = (const float*)d_in[12];
    const float* be0 = (const float*)d_in[13];
    const float* g1  = (const float*)d_in[14];
    const float* be1 = (const float*)d_in[15];
    float* out = (float*)d_out;

    int N = in_sizes[0] / 128;
    int E = in_sizes[2];

    float *h, *stats0, *stats1;
    __nv_bfloat16 *xH, *xL, *mH, *mL, *yH, *yL, *BH, *BL;
    cudaGetSymbolAddress((void**)&h,  g_h);
    cudaGetSymbolAddress((void**)&xH, g_xH);
    cudaGetSymbolAddress((void**)&xL, g_xL);
    cudaGetSymbolAddress((void**)&mH, g_mH);
    cudaGetSymbolAddress((void**)&mL, g_mL);
    cudaGetSymbolAddress((void**)&yH, g_yH);
    cudaGetSymbolAddress((void**)&yL, g_yL);
    cudaGetSymbolAddress((void**)&BH, g_BH);
    cudaGetSymbolAddress((void**)&BL, g_BL);
    cudaGetSymbolAddress((void**)&stats0, g_statsA);
    stats1 = stats0 + 256;

    constexpr int SM128 = 2 * (2 * 128 * 80 + 2 * 128 * 80);  // 81920
    constexpr int SM64  = 2 * (2 * 128 * 80 + 2 * 64 * 80);   // 61440
    cudaFuncSetAttribute(gemm2<128, true>, cudaFuncAttributeMaxDynamicSharedMemorySize, SM128);
    cudaFuncSetAttribute(gemm2<64, false>, cudaFuncAttributeMaxDynamicSharedMemorySize, SM64);

    const int T = 256;
    int gE = (E + T - 1) / T;
    int gW = (N + 7) / 8;
    int gGemm = (N + 127) / 128;
    int gApply = (N * 32 + T - 1) / T;
    float invM = 1.0f / (float)N;

    // prep: x split, weight transpose+split, deg/stats zero
    prep_kernel<<<gApply, T>>>(x, Wl0, Wr0, Wl1, Wr1, Wl2, Wr2, N * 32);
    // CSR build (graph shared by all 3 layers)
    count_deg_kernel<<<gE, T>>>(ei + E, E);
    scan_kernel<<<1, 1024>>>(N);
    scatter_kernel<<<gE, T>>>(ei, ei + E, ew, E);

    // ----- layer 0 -----
    aggregate_kernel<false><<<gW, T>>>(x, nullptr, nullptr, nullptr, invM, N);
    gemm2<128, true><<<gGemm, T, SM128>>>(mH, mL, xH, xL, BH, BL, b0, h, stats0, N);

    // ----- layer 1 -----
    bnapply_kernel<<<gApply, T>>>(stats0, g0, be0, invM, N * 32);
    aggregate_kernel<true><<<gW, T>>>(h, stats0, g0, be0, invM, N);
    gemm2<128, true><<<gGemm, T, SM128>>>(mH, mL, yH, yL, BH + 32768, BL + 32768, b1, h, stats1, N);

    // ----- layer 2 (output, 64 cols) -----
    bnapply_kernel<<<gApply, T>>>(stats1, g1, be1, invM, N * 32);
    aggregate_kernel<true><<<gW, T>>>(h, stats1, g1, be1, invM, N);
    gemm2<64, false><<<gGemm, T, SM64>>>(mH, mL, yH, yL, BH + 65536, BL + 65536, b2, out, nullptr, N);
}

// round 5
// speedup vs baseline: 1.5689x; 1.0695x over previous
#include <cuda_runtime.h>
#include <cuda_bf16.h>
#include <cstdint>

#define NNODES 50000
#define NEDGES 600000

// ---------------- scratch (device globals) -------------------------------------
__device__ int   g_deg[NNODES];          // zero-initialized; re-zeroed by scan_final
__device__ int   g_rowoff[NNODES + 1];
__device__ int   g_woff[NNODES];
__device__ int   g_bsum[64];
__device__ int   g_boff[64];
__device__ int2  g_edge[NEDGES];         // (src, w_bits)
__device__ float g_h[NNODES * 128];
__device__ __nv_bfloat16 g_xH[NNODES * 128], g_xL[NNODES * 128];
__device__ __nv_bfloat16 g_mH[NNODES * 128], g_mL[NNODES * 128];
__device__ __nv_bfloat16 g_yH[NNODES * 128], g_yL[NNODES * 128];
__device__ __nv_bfloat16 g_BH[81920], g_BL[81920];   // W0(32768) W1(32768) W2(16384), [n][k]
__device__ float g_statsA[512];          // layer0: [0,256) ; layer1: [256,512)

// ---------------- helpers ------------------------------------------------------
__device__ __forceinline__ uint32_t smem_u32(const void* p) {
    uint32_t a;
    asm("{ .reg .u64 t; cvta.to.shared.u64 t, %1; cvt.u32.u64 %0, t; }" : "=r"(a) : "l"(p));
    return a;
}
__device__ __forceinline__ void ldsm_x4(uint32_t addr, uint32_t r[4]) {
    asm volatile("ldmatrix.sync.aligned.m8n8.x4.shared.b16 {%0,%1,%2,%3}, [%4];"
        : "=r"(r[0]), "=r"(r[1]), "=r"(r[2]), "=r"(r[3]) : "r"(addr));
}
__device__ __forceinline__ void mma16816(float c[4], const uint32_t a[4], uint32_t b0, uint32_t b1) {
    asm volatile("mma.sync.aligned.m16n8k16.row.col.f32.bf16.bf16.f32 "
        "{%0,%1,%2,%3}, {%4,%5,%6,%7}, {%8,%9}, {%0,%1,%2,%3};"
        : "+f"(c[0]), "+f"(c[1]), "+f"(c[2]), "+f"(c[3])
        : "r"(a[0]), "r"(a[1]), "r"(a[2]), "r"(a[3]), "r"(b0), "r"(b1));
}
__device__ __forceinline__ void cpa16(uint32_t dst, const void* src, bool pred) {
    int sz = pred ? 16 : 0;
    asm volatile("cp.async.cg.shared.global [%0], [%1], 16, %2;"
        :: "r"(dst), "l"(src), "r"(sz) : "memory");
}
__device__ __forceinline__ void split2(float a, float b, uint32_t& hi, uint32_t& lo) {
    __nv_bfloat162 h = __floats2bfloat162_rn(a, b);
    float ha = __bfloat162float(h.x), hb = __bfloat162float(h.y);
    __nv_bfloat162 l = __floats2bfloat162_rn(a - ha, b - hb);
    hi = *reinterpret_cast<uint32_t*>(&h);
    lo = *reinterpret_cast<uint32_t*>(&l);
}
__device__ __forceinline__ void bn_coef(const float* __restrict__ stats,
                                        const float* __restrict__ gamma,
                                        const float* __restrict__ beta,
                                        float invM, int c, float& sc, float& sh) {
    float mu  = stats[c] * invM;
    float var = stats[128 + c] * invM - mu * mu;
    float s = gamma[c] * rsqrtf(var + 1e-5f);
    sc = s;
    sh = beta[c] - mu * s;
}

// ---------------- prep: x split + weights + degree count + stats zero ----------
__global__ void prep_kernel(const float* __restrict__ x,
                            const int* __restrict__ dst,
                            const float* __restrict__ Wl0, const float* __restrict__ Wr0,
                            const float* __restrict__ Wl1, const float* __restrict__ Wr1,
                            const float* __restrict__ Wl2, const float* __restrict__ Wr2,
                            int n4, int E) {
    int gid = blockIdx.x * blockDim.x + threadIdx.x;
    if (gid < n4) {
        float4 v = ((const float4*)x)[gid];
        uint32_t h01, l01, h23, l23;
        split2(v.x, v.y, h01, l01);
        split2(v.z, v.w, h23, l23);
        ((uint2*)g_xH)[gid] = make_uint2(h01, h23);
        ((uint2*)g_xL)[gid] = make_uint2(l01, l23);
    }
    if (gid < E) atomicAdd(&g_deg[dst[gid]], 1);   // g_deg zeroed by prior scan_final
    if (gid < 512) g_statsA[gid] = 0.f;
    if (gid < 81920) {
        const float *Wl, *Wr; int TN, t, off;
        if (gid < 32768)      { Wl = Wl0; Wr = Wr0; TN = 128; t = gid;         off = 0; }
        else if (gid < 65536) { Wl = Wl1; Wr = Wr1; TN = 128; t = gid - 32768; off = 32768; }
        else                  { Wl = Wl2; Wr = Wr2; TN = 64;  t = gid - 65536; off = 65536; }
        int n = t >> 8, k = t & 255;
        float v = (k < 128) ? Wl[k * TN + n] : Wr[(k - 128) * TN + n];
        __nv_bfloat16 h = __float2bfloat16_rn(v);
        g_BH[off + t] = h;
        g_BL[off + t] = __float2bfloat16_rn(v - __bfloat162float(h));
    }
}

// ---------------- multi-block scan ---------------------------------------------
__global__ void scan_reduce(int n) {        // grid: ceil(n/1024), block 1024
    int i = blockIdx.x * 1024 + threadIdx.x;
    int v = (i < n) ? g_deg[i] : 0;
    #pragma unroll
    for (int o = 16; o; o >>= 1) v += __shfl_xor_sync(0xFFFFFFFFu, v, o);
    __shared__ int ws[32];
    if ((threadIdx.x & 31) == 0) ws[threadIdx.x >> 5] = v;
    __syncthreads();
    if (threadIdx.x < 32) {
        int s = ws[threadIdx.x];
        #pragma unroll
        for (int o = 16; o; o >>= 1) s += __shfl_xor_sync(0xFFFFFFFFu, s, o);
        if (threadIdx.x == 0) g_bsum[blockIdx.x] = s;
    }
}
__global__ void scan_mid(int nb, int n) {   // 1 block, 64 threads
    __shared__ int sm[64];
    int t = threadIdx.x;
    sm[t] = (t < nb) ? g_bsum[t] : 0;
    __syncthreads();
    if (t == 0) {
        int run = 0;
        for (int i = 0; i < nb; i++) { int v = sm[i]; sm[i] = run; run += v; }
        g_rowoff[n] = run;
    }
    __syncthreads();
    if (t < nb) g_boff[t] = sm[t];
}
__global__ void scan_final(int n) {         // grid: ceil(n/1024), block 1024
    int tid = threadIdx.x, lane = tid & 31, wid = tid >> 5;
    int i = blockIdx.x * 1024 + tid;
    int v = (i < n) ? g_deg[i] : 0;
    int x = v;
    #pragma unroll
    for (int o = 1; o < 32; o <<= 1) {
        int t2 = __shfl_up_sync(0xFFFFFFFFu, x, o);
        if (lane >= o) x += t2;
    }
    __shared__ int ws[32];
    if (lane == 31) ws[wid] = x;
    __syncthreads();
    if (wid == 0) {
        int y = (lane < 32) ? ws[lane] : 0;
        #pragma unroll
        for (int o = 1; o < 32; o <<= 1) {
            int t2 = __shfl_up_sync(0xFFFFFFFFu, y, o);
            if (lane >= o) y += t2;
        }
        ws[lane] = y;
    }
    __syncthreads();
    int excl = x - v + (wid ? ws[wid - 1] : 0) + g_boff[blockIdx.x];
    if (i < n) {
        g_rowoff[i] = excl;
        g_woff[i]   = excl;
        g_deg[i]    = 0;     // ready for next replay
    }
}
__global__ void scatter_kernel(const int* __restrict__ src, const int* __restrict__ dst,
                               const float* __restrict__ w, int e) {
    int i = blockIdx.x * blockDim.x + threadIdx.x;
    if (i < e) {
        int d = dst[i];
        int p = atomicAdd(&g_woff[d], 1);
        g_edge[p] = make_int2(src[i], __float_as_int(w[i]));
    }
}

// ---------------- fused aggregate (+BN gather) & bnapply ------------------------
// blocks [0, nAgg): warp-per-node aggregation (optionally BN+ReLU on gathered vals)
// blocks [nAgg, nAgg+nApply): elementwise h -> yH/yL (BN+ReLU + bf16 split)
template <bool BN>
__global__ void layer_mid(const float* __restrict__ X,
                          const float* __restrict__ stats,
                          const float* __restrict__ gamma,
                          const float* __restrict__ beta,
                          float invM, int n, int nAgg) {
    int tid = threadIdx.x;
    if ((int)blockIdx.x >= nAgg) {
        if (!BN) return;
        int i = (blockIdx.x - nAgg) * 256 + tid;
        if (i >= n * 32) return;
        int c0 = (i & 31) * 4;
        float4 sc, sh;
        bn_coef(stats, gamma, beta, invM, c0 + 0, sc.x, sh.x);
        bn_coef(stats, gamma, beta, invM, c0 + 1, sc.y, sh.y);
        bn_coef(stats, gamma, beta, invM, c0 + 2, sc.z, sh.z);
        bn_coef(stats, gamma, beta, invM, c0 + 3, sc.w, sh.w);
        float4 v = ((const float4*)g_h)[i];
        float4 r;
        r.x = fmaxf(fmaf(v.x, sc.x, sh.x), 0.f);
        r.y = fmaxf(fmaf(v.y, sc.y, sh.y), 0.f);
        r.z = fmaxf(fmaf(v.z, sc.z, sh.z), 0.f);
        r.w = fmaxf(fmaf(v.w, sc.w, sh.w), 0.f);
        uint32_t h01, l01, h23, l23;
        split2(r.x, r.y, h01, l01);
        split2(r.z, r.w, h23, l23);
        ((uint2*)g_yH)[i] = make_uint2(h01, h23);
        ((uint2*)g_yL)[i] = make_uint2(l01, l23);
        return;
    }

    int node = blockIdx.x * 8 + (tid >> 5);
    int lane = tid & 31;
    if (node >= n) return;

    float4 sc = make_float4(1.f, 1.f, 1.f, 1.f), sh = make_float4(0.f, 0.f, 0.f, 0.f);
    if (BN) {
        bn_coef(stats, gamma, beta, invM, lane * 4 + 0, sc.x, sh.x);
        bn_coef(stats, gamma, beta, invM, lane * 4 + 1, sc.y, sh.y);
        bn_coef(stats, gamma, beta, invM, lane * 4 + 2, sc.z, sh.z);
        bn_coef(stats, gamma, beta, invM, lane * 4 + 3, sc.w, sh.w);
    }

    int beg = g_rowoff[node], end = g_rowoff[node + 1];
    const float4* X4 = (const float4*)X;
    float4 acc = make_float4(0.f, 0.f, 0.f, 0.f);
    int e = beg;

    auto accum = [&](int2 ed) {
        float w = __int_as_float(ed.y);
        float4 v = X4[(long)ed.x * 32 + lane];
        if (BN) {
            v.x = fmaxf(fmaf(v.x, sc.x, sh.x), 0.f);
            v.y = fmaxf(fmaf(v.y, sc.y, sh.y), 0.f);
            v.z = fmaxf(fmaf(v.z, sc.z, sh.z), 0.f);
            v.w = fmaxf(fmaf(v.w, sc.w, sh.w), 0.f);
        }
        acc.x += w * v.x; acc.y += w * v.y; acc.z += w * v.z; acc.w += w * v.w;
    };

    for (; e + 3 < end; e += 4) {
        int2 e0 = g_edge[e], e1 = g_edge[e + 1], e2 = g_edge[e + 2], e3 = g_edge[e + 3];
        accum(e0); accum(e1); accum(e2); accum(e3);
    }
    for (; e < end; e++) accum(g_edge[e]);

    float inv = 1.0f / fmaxf((float)(end - beg), 1.0f);
    acc.x *= inv; acc.y *= inv; acc.z *= inv; acc.w *= inv;
    uint32_t h01, l01, h23, l23;
    split2(acc.x, acc.y, h01, l01);
    split2(acc.z, acc.w, h23, l23);
    ((uint2*)g_mH)[(long)node * 32 + lane] = make_uint2(h01, h23);
    ((uint2*)g_mL)[(long)node * 32 + lane] = make_uint2(l01, l23);
}

// ---------------- mma.sync GEMM: shared A-hi across B-hi/B-lo terms -------------
template <int TN, bool STATS>
__global__ void __launch_bounds__(256)
gemm2(const __nv_bfloat16* __restrict__ mH, const __nv_bfloat16* __restrict__ mL,
      const __nv_bfloat16* __restrict__ rH, const __nv_bfloat16* __restrict__ rL,
      const __nv_bfloat16* __restrict__ BH, const __nv_bfloat16* __restrict__ BL,
      const float* __restrict__ bias, float* __restrict__ C,
      float* __restrict__ stats, int M) {
    constexpr int NWC = TN / 2;
    constexpr int NF  = NWC / 8;
    constexpr int offAhi = 0;
    constexpr int offAlo = 128 * 80;
    constexpr int offBhi = 2 * 128 * 80;
    constexpr int offBlo = 2 * 128 * 80 + TN * 80;
    constexpr int STAGE  = 2 * 128 * 80 + 2 * TN * 80;

    extern __shared__ __align__(16) char smem[];
    const uint32_t sbase = smem_u32(smem);

    const int tid = threadIdx.x;
    const int lane = tid & 31, wid = tid >> 5;
    const int wm = wid & 3, wn = wid >> 2;
    const int row0 = blockIdx.x * 128;

    float acc[2][NF][4];
    #pragma unroll
    for (int mb = 0; mb < 2; mb++)
        #pragma unroll
        for (int f = 0; f < NF; f++)
            #pragma unroll
            for (int q = 0; q < 4; q++) acc[mb][f][q] = 0.f;

    auto load_chunk = [&](int ch, int buf) {
        const int half = ch >> 2, q = ch & 3;
        const __nv_bfloat16* Ah = half ? rH : mH;
        const __nv_bfloat16* Al = half ? rL : mL;
        const int acol = q * 32;
        const int bcol = half * 128 + q * 32;
        const uint32_t base = sbase + buf * STAGE;
        #pragma unroll
        for (int t = 0; t < 2; t++) {
            int idx = tid + t * 256;
            int r = idx >> 2, c = idx & 3;
            int gr = row0 + r;
            const long aoff = (long)gr * 128 + acol + c * 8;
            cpa16(base + offAhi + r * 80 + c * 16, Ah + aoff, gr < M);
            cpa16(base + offAlo + r * 80 + c * 16, Al + aoff, gr < M);
        }
        #pragma unroll
        for (int t = 0; t < TN / 64; t++) {
            int idx = tid + t * 256;
            int n = idx >> 2, c = idx & 3;
            const long boff = (long)n * 256 + bcol + c * 8;
            cpa16(base + offBhi + n * 80 + c * 16, BH + boff, true);
            cpa16(base + offBlo + n * 80 + c * 16, BL + boff, true);
        }
        asm volatile("cp.async.commit_group;" ::: "memory");
    };

    load_chunk(0, 0);

    for (int ch = 0; ch < 8; ch++) {
        const int buf = ch & 1;
        if (ch + 1 < 8) {
            load_chunk(ch + 1, buf ^ 1);
            asm volatile("cp.async.wait_group 1;" ::: "memory");
        } else {
            asm volatile("cp.async.wait_group 0;" ::: "memory");
        }
        __syncthreads();
        const uint32_t base = sbase + buf * STAGE;

        #pragma unroll
        for (int ks = 0; ks < 2; ks++) {
            uint32_t aH2[2][4], aL2[2][4];
            #pragma unroll
            for (int mb = 0; mb < 2; mb++) {
                uint32_t rterm = (wm * 32 + mb * 16 + (lane & 15)) * 80
                               + ks * 32 + ((lane >> 4) << 4);
                ldsm_x4(base + offAhi + rterm, aH2[mb]);
                ldsm_x4(base + offAlo + rterm, aL2[mb]);
            }
            #pragma unroll
            for (int f = 0; f < NF / 2; f++) {
                int n = wn * NWC + f * 16 + (lane & 7) + ((lane >> 3) & 1) * 8;
                uint32_t boff = n * 80 + ks * 32 + ((lane >> 4) << 4);
                uint32_t bH[4], bL[4];
                ldsm_x4(base + offBhi + boff, bH);
                ldsm_x4(base + offBlo + boff, bL);
                #pragma unroll
                for (int mb = 0; mb < 2; mb++) {
                    mma16816(acc[mb][2 * f],     aH2[mb], bH[0], bH[2]);
                    mma16816(acc[mb][2 * f + 1], aH2[mb], bH[1], bH[3]);
                    mma16816(acc[mb][2 * f],     aL2[mb], bH[0], bH[2]);
                    mma16816(acc[mb][2 * f + 1], aL2[mb], bH[1], bH[3]);
                    mma16816(acc[mb][2 * f],     aH2[mb], bL[0], bL[2]);
                    mma16816(acc[mb][2 * f + 1], aH2[mb], bL[1], bL[3]);
                }
            }
        }
        __syncthreads();
    }

    const int rA = row0 + wm * 32 + (lane >> 2);
    const int cbase = wn * NWC + (lane & 3) * 2;
    #pragma unroll
    for (int nf = 0; nf < NF; nf++) {
        int col = cbase + nf * 8;
        float bx = bias[col], by = bias[col + 1];
        float s0 = 0.f, q0 = 0.f, s1 = 0.f, q1 = 0.f;
        #pragma unroll
        for (int mb = 0; mb < 2; mb++) {
            int r0r = rA + mb * 16;
            if (r0r < M) {
                float vx = acc[mb][nf][0] + bx, vy = acc[mb][nf][1] + by;
                *(float2*)(C + (long)r0r * TN + col) = make_float2(vx, vy);
                if (STATS) { s0 += vx; q0 += vx * vx; s1 += vy; q1 += vy * vy; }
            }
            int r1r = r0r + 8;
            if (r1r < M) {
                float vx = acc[mb][nf][2] + bx, vy = acc[mb][nf][3] + by;
                *(float2*)(C + (long)r1r * TN + col) = make_float2(vx, vy);
                if (STATS) { s0 += vx; q0 += vx * vx; s1 += vy; q1 += vy * vy; }
            }
        }
        if (STATS) {
            #pragma unroll
            for (int o = 4; o < 32; o <<= 1) {
                s0 += __shfl_xor_sync(0xFFFFFFFFu, s0, o);
                q0 += __shfl_xor_sync(0xFFFFFFFFu, q0, o);
                s1 += __shfl_xor_sync(0xFFFFFFFFu, s1, o);
                q1 += __shfl_xor_sync(0xFFFFFFFFu, q1, o);
            }
            if ((lane >> 2) == 0) {
                atomicAdd(&stats[col], s0);
                atomicAdd(&stats[128 + col], q0);
                atomicAdd(&stats[col + 1], s1);
                atomicAdd(&stats[128 + col + 1], q1);
            }
        }
    }
}

// ---------------- launch --------------------------------------------------------
extern "C" void kernel_launch(void* const* d_in, const int* in_sizes, int n_in,
                              void* d_out, int out_size) {
    const float* x   = (const float*)d_in[0];
    const int*   ei  = (const int*)d_in[1];
    const float* ew  = (const float*)d_in[2];
    const float* Wl0 = (const float*)d_in[3];
    const float* Wr0 = (const float*)d_in[4];
    const float* b0  = (const float*)d_in[5];
    const float* Wl1 = (const float*)d_in[6];
    const float* Wr1 = (const float*)d_in[7];
    const float* b1  = (const float*)d_in[8];
    const float* Wl2 = (const float*)d_in[9];
    const float* Wr2 = (const float*)d_in[10];
    const float* b2  = (const float*)d_in[11];
    const float* g0  = (const float*)d_in[12];
    const float* be0 = (const float*)d_in[13];
    const float* g1  = (const float*)d_in[14];
    const float* be1 = (const float*)d_in[15];
    float* out = (float*)d_out;

    int N = in_sizes[0] / 128;
    int E = in_sizes[2];

    float *h, *stats0, *stats1;
    __nv_bfloat16 *xH, *xL, *mH, *mL, *yH, *yL, *BH, *BL;
    cudaGetSymbolAddress((void**)&h,  g_h);
    cudaGetSymbolAddress((void**)&xH, g_xH);
    cudaGetSymbolAddress((void**)&xL, g_xL);
    cudaGetSymbolAddress((void**)&mH, g_mH);
    cudaGetSymbolAddress((void**)&mL, g_mL);
    cudaGetSymbolAddress((void**)&yH, g_yH);
    cudaGetSymbolAddress((void**)&yL, g_yL);
    cudaGetSymbolAddress((void**)&BH, g_BH);
    cudaGetSymbolAddress((void**)&BL, g_BL);
    cudaGetSymbolAddress((void**)&stats0, g_statsA);
    stats1 = stats0 + 256;

    constexpr int SM128 = 2 * (2 * 128 * 80 + 2 * 128 * 80);  // 81920
    constexpr int SM64  = 2 * (2 * 128 * 80 + 2 * 64 * 80);   // 61440
    cudaFuncSetAttribute(gemm2<128, true>, cudaFuncAttributeMaxDynamicSharedMemorySize, SM128);
    cudaFuncSetAttribute(gemm2<64, false>, cudaFuncAttributeMaxDynamicSharedMemorySize, SM64);

    const int T = 256;
    int gE = (E + T - 1) / T;
    int gW = (N + 7) / 8;                 // 6250 aggregate blocks
    int gGemm = (N + 127) / 128;
    int gApply = (N * 32 + T - 1) / T;    // 6250 elementwise blocks
    int gScan = (N + 1023) / 1024;        // 49
    float invM = 1.0f / (float)N;

    // prep (x split, weights, count_deg, stats zero) + CSR build
    prep_kernel<<<gApply, T>>>(x, ei + E, Wl0, Wr0, Wl1, Wr1, Wl2, Wr2, N * 32, E);
    scan_reduce<<<gScan, 1024>>>(N);
    scan_mid<<<1, 64>>>(gScan, N);
    scan_final<<<gScan, 1024>>>(N);
    scatter_kernel<<<gE, T>>>(ei, ei + E, ew, E);

    // ----- layer 0 -----
    layer_mid<false><<<gW, T>>>(x, nullptr, nullptr, nullptr, invM, N, gW);
    gemm2<128, true><<<gGemm, T, SM128>>>(mH, mL, xH, xL, BH, BL, b0, h, stats0, N);

    // ----- layer 1 (fused bnapply + aggregate-with-BN) -----
    layer_mid<true><<<gW + gApply, T>>>(h, stats0, g0, be0, invM, N, gW);
    gemm2<128, true><<<gGemm, T, SM128>>>(mH, mL, yH, yL, BH + 32768, BL + 32768, b1, h, stats1, N);

    // ----- layer 2 (output, 64 cols) -----
    layer_mid<true><<<gW + gApply, T>>>(h, stats1, g1, be1, invM, N, gW);
    gemm2<64, false><<<gGemm, T, SM64>>>(mH, mL, yH, yL, BH + 65536, BL + 65536, b2, out, nullptr, N);
}